// round 7
// baseline (speedup 1.0000x reference)
#include <cuda_runtime.h>
#include <cuda_bf16.h>
#include <cuda_fp16.h>
#include <cstdint>

#define MAXN 50048
#define MAXE 860032
#define IN_DIM 128
#define HEADS 4
#define OUT_DIM 64
#define FTOT 256

// ---------------- scratch ----------------
__device__ unsigned g_hh[(size_t)MAXN * 128];   // h as half2 pairs: 25.6 MB
__device__ float4 g_asrc[MAXN];
__device__ float4 g_adst[MAXN];
__device__ int    g_src[MAXE];
__device__ int    g_cnt[MAXN];
__device__ int    g_off[MAXN + 1];
__device__ int    g_cur[MAXN];
__device__ int    g_bsum[256];
__device__ int    g_boff[256];
__device__ __align__(16) __nv_bfloat16 g_wthi[FTOT * IN_DIM]; // W^T hi: [n][k]
__device__ __align__(16) __nv_bfloat16 g_wtlo[FTOT * IN_DIM]; // W^T lo

__device__ __forceinline__ float lrelu(float e) {
    return e > 0.0f ? e : 0.2f * e;
}

__device__ __forceinline__ int edge_stride(const unsigned* w) {
    int is64 = 1;
    #pragma unroll 1
    for (int j = 1; j < 64; j += 2)
        if (w[j] != 0u) { is64 = 0; break; }
    return is64 ? 2 : 1;
}

// ---------------- 1: zero degree counters ----------------
__global__ void zero_cnt_kernel(int N) {
    int i = blockIdx.x * blockDim.x + threadIdx.x;
    if (i < N) g_cnt[i] = 0;
}

// ---------------- 2: histogram ----------------
__global__ void hist_kernel(const unsigned* __restrict__ w, int E, int N) {
    __shared__ int s_st;
    if (threadIdx.x == 0) s_st = edge_stride(w);
    __syncthreads();
    int st = s_st;
    int i = blockIdx.x * blockDim.x + threadIdx.x;
    if (i >= E + N) return;
    int d = (i < E) ? (int)w[st * E + st * i] : (i - E);
    atomicAdd(&g_cnt[d], 1);
}

// ---------------- 3: W transpose + bf16 hi/lo split ----------------
__global__ void wt_kernel(const float* __restrict__ W) {
    int i = blockIdx.x * 256 + threadIdx.x;     // 0..32767
    int k = i & 127, n = i >> 7;
    float v = __ldg(W + (size_t)k * FTOT + n);
    __nv_bfloat16 h = __float2bfloat16_rn(v);
    g_wthi[i] = h;
    g_wtlo[i] = __float2bfloat16_rn(v - __bfloat162float(h));
}

// ---------------- 4: GEMM on HMMA + ldmatrix (split-bf16, 3 passes) --------
// Block: 256 thr (8 warps = 4m x 2n), tile 128 rows x 64 cols (one head).
// Whole K=128 staged once in SMEM (pitch 136 halves -> conflict-free LDSM).
// D = A_hi@B_hi + A_hi@B_lo + A_lo@B_hi, fp32 accum.
#define PA 136
#define A_BYTES (128 * PA * 2)                  // 34816
#define B_BYTES (64 * PA * 2)                   // 17408
#define SM_A_HI 0
#define SM_A_LO A_BYTES
#define SM_B_HI (2 * A_BYTES)
#define SM_B_LO (2 * A_BYTES + B_BYTES)
#define SM_ATT  (2 * A_BYTES + 2 * B_BYTES)
#define SMEM_BYTES (SM_ATT + 512)

#define LDSM_X4(r, a)                                                         \
    asm volatile("ldmatrix.sync.aligned.m8n8.x4.shared.b16 {%0,%1,%2,%3}, [%4];" \
        : "=r"((r)[0]), "=r"((r)[1]), "=r"((r)[2]), "=r"((r)[3]) : "r"(a))

__global__ void __launch_bounds__(256, 2)
gemm_kernel(const float* __restrict__ x,
            const float* __restrict__ att_src,
            const float* __restrict__ att_dst, int N) {
    extern __shared__ __align__(16) char sm[];
    const uint32_t smb = (uint32_t)__cvta_generic_to_shared(sm);
    float* attm = (float*)(sm + SM_ATT);

    const int tid = threadIdx.x;
    const int lane = tid & 31, wid = tid >> 5;
    const int mw = wid & 3, nw = wid >> 2;
    const int m_base = blockIdx.x * 128, head = blockIdx.y;
    const int n_base = head * OUT_DIM;

    if (tid < 64) {
        attm[tid] = __ldg(att_src + n_base + tid);
        attm[64 + tid] = __ldg(att_dst + n_base + tid);
    }

    // ---- A fill: 128 rows x 128 k -> bf16 hi/lo ----
    {
        const int r = tid >> 1, seg = tid & 1;
        int grow = m_base + r;
        if (grow >= N) grow = N - 1;
        const float4* xs = (const float4*)(x + (size_t)grow * IN_DIM + seg * 64);
        char* ah = sm + SM_A_HI + (r * PA + seg * 64) * 2;
        char* al = sm + SM_A_LO + (r * PA + seg * 64) * 2;
        #pragma unroll
        for (int i = 0; i < 16; i++) {
            float4 v = __ldg(xs + i);
            __nv_bfloat162 h01, h23, l01, l23;
            h01.x = __float2bfloat16_rn(v.x);
            h01.y = __float2bfloat16_rn(v.y);
            h23.x = __float2bfloat16_rn(v.z);
            h23.y = __float2bfloat16_rn(v.w);
            l01.x = __float2bfloat16_rn(v.x - __bfloat162float(h01.x));
            l01.y = __float2bfloat16_rn(v.y - __bfloat162float(h01.y));
            l23.x = __float2bfloat16_rn(v.z - __bfloat162float(h23.x));
            l23.y = __float2bfloat16_rn(v.w - __bfloat162float(h23.y));
            uint2 uh, ul;
            uh.x = *reinterpret_cast<unsigned*>(&h01);
            uh.y = *reinterpret_cast<unsigned*>(&h23);
            ul.x = *reinterpret_cast<unsigned*>(&l01);
            ul.y = *reinterpret_cast<unsigned*>(&l23);
            *(uint2*)(ah + i * 8) = uh;
            *(uint2*)(al + i * 8) = ul;
        }
    }
    // ---- B fill: 64 n-rows x 128 k from pre-split W^T ----
    {
        const int bn = tid >> 2, q = tid & 3;
        const uint4* shh = (const uint4*)(g_wthi + (size_t)(n_base + bn) * IN_DIM);
        const uint4* shl = (const uint4*)(g_wtlo + (size_t)(n_base + bn) * IN_DIM);
        uint4* dhh = (uint4*)(sm + SM_B_HI + bn * PA * 2);
        uint4* dhl = (uint4*)(sm + SM_B_LO + bn * PA * 2);
        #pragma unroll
        for (int j = 0; j < 4; j++) {
            dhh[q * 4 + j] = __ldg(shh + q * 4 + j);
            dhl[q * 4 + j] = __ldg(shl + q * 4 + j);
        }
    }
    __syncthreads();

    // ---- ldmatrix per-lane base addresses (bytes) ----
    const int quad = lane >> 3, lrow = lane & 7;
    uint32_t aAddr[2], bAddr[2];
    #pragma unroll
    for (int mt = 0; mt < 2; mt++) {
        int row = mw * 32 + mt * 16 + (quad & 1) * 8 + lrow;
        int koff = (quad >> 1) * 8;
        aAddr[mt] = smb + SM_A_HI + (row * PA + koff) * 2;
    }
    #pragma unroll
    for (int p = 0; p < 2; p++) {
        int n = nw * 32 + p * 16 + (quad >> 1) * 8 + lrow;
        int koff = (quad & 1) * 8;
        bAddr[p] = smb + SM_B_HI + (n * PA + koff) * 2;
    }

    float acc[2][4][4];
    #pragma unroll
    for (int mt = 0; mt < 2; mt++)
        #pragma unroll
        for (int nt = 0; nt < 4; nt++)
            #pragma unroll
            for (int c = 0; c < 4; c++) acc[mt][nt][c] = 0.0f;

    // ---- 3 passes x 8 k16 steps ----
    #pragma unroll
    for (int pass = 0; pass < 3; pass++) {
        const uint32_t aOff = (pass == 2) ? (uint32_t)A_BYTES : 0u;
        const uint32_t bOff = (pass == 1) ? (uint32_t)B_BYTES : 0u;
        #pragma unroll
        for (int kk = 0; kk < 8; kk++) {
            unsigned a0[4], a1[4], b0[4], b1[4];
            LDSM_X4(a0, aAddr[0] + aOff + kk * 32);
            LDSM_X4(a1, aAddr[1] + aOff + kk * 32);
            LDSM_X4(b0, bAddr[0] + bOff + kk * 32);
            LDSM_X4(b1, bAddr[1] + bOff + kk * 32);
            const unsigned* aa[2] = {a0, a1};
            const unsigned* bb[4] = {b0, b0 + 2, b1, b1 + 2};
            #pragma unroll
            for (int mt = 0; mt < 2; mt++)
                #pragma unroll
                for (int nt = 0; nt < 4; nt++)
                    asm volatile(
                        "mma.sync.aligned.m16n8k16.row.col.f32.bf16.bf16.f32 "
                        "{%0,%1,%2,%3}, {%4,%5,%6,%7}, {%8,%9}, {%0,%1,%2,%3};"
                        : "+f"(acc[mt][nt][0]), "+f"(acc[mt][nt][1]),
                          "+f"(acc[mt][nt][2]), "+f"(acc[mt][nt][3])
                        : "r"(aa[mt][0]), "r"(aa[mt][1]), "r"(aa[mt][2]), "r"(aa[mt][3]),
                          "r"(bb[nt][0]), "r"(bb[nt][1]));
        }
    }

    // ---- C -> smem (fp32, pitch 66) over A region ----
    __syncthreads();
    float* Csm = (float*)(sm);                   // 128 x 66 floats = 33792 B
    #pragma unroll
    for (int mt = 0; mt < 2; mt++)
        #pragma unroll
        for (int nt = 0; nt < 4; nt++) {
            int r0 = mw * 32 + mt * 16 + (lane >> 2);
            int c = nw * 32 + nt * 8 + (lane & 3) * 2;
            *(float2*)(Csm + r0 * 66 + c) =
                make_float2(acc[mt][nt][0], acc[mt][nt][1]);
            *(float2*)(Csm + (r0 + 8) * 66 + c) =
                make_float2(acc[mt][nt][2], acc[mt][nt][3]);
        }
    __syncthreads();

    // ---- att logits (fp32) + fp16 h store ----
    {
        int r = tid >> 1, seg = tid & 1;
        int row = m_base + r;
        const float2* crow = (const float2*)(Csm + r * 66) + seg * 16;
        const float* asv = attm + seg * 32;
        const float* adv = attm + 64 + seg * 32;
        float s1 = 0.f, s2 = 0.f;
        uint4* dst = (uint4*)(g_hh + (size_t)row * 128) + head * 8 + seg * 4;
        #pragma unroll
        for (int q = 0; q < 4; q++) {
            uint4 pk;
            unsigned* pw = (unsigned*)&pk;
            #pragma unroll
            for (int j = 0; j < 4; j++) {
                float2 f = crow[q * 4 + j];
                s1 = fmaf(f.x, asv[q * 8 + j * 2], s1);
                s1 = fmaf(f.y, asv[q * 8 + j * 2 + 1], s1);
                s2 = fmaf(f.x, adv[q * 8 + j * 2], s2);
                s2 = fmaf(f.y, adv[q * 8 + j * 2 + 1], s2);
                __half2 hv = __floats2half2_rn(f.x, f.y);
                pw[j] = *reinterpret_cast<unsigned*>(&hv);
            }
            dst[q] = pk;
        }
        s1 += __shfl_xor_sync(0xffffffffu, s1, 1);
        s2 += __shfl_xor_sync(0xffffffffu, s2, 1);
        if (seg == 0 && row < N) {
            ((float*)&g_asrc[row])[head] = s1;
            ((float*)&g_adst[row])[head] = s2;
        }
    }
}

// ---------------- 5: three-phase exclusive scan ----------------
__global__ void scan_a_kernel(int N) {
    __shared__ int sh[256];
    int idx = blockIdx.x * 256 + threadIdx.x;
    int v = (idx < N) ? g_cnt[idx] : 0;
    sh[threadIdx.x] = v;
    __syncthreads();
    #pragma unroll
    for (int off = 128; off >= 1; off >>= 1) {
        if (threadIdx.x < off) sh[threadIdx.x] += sh[threadIdx.x + off];
        __syncthreads();
    }
    if (threadIdx.x == 0) g_bsum[blockIdx.x] = sh[0];
}

__global__ void scan_b_kernel(int GB) {
    __shared__ int sh[256];
    int t = threadIdx.x;
    int v = (t < GB) ? g_bsum[t] : 0;
    sh[t] = v;
    __syncthreads();
    #pragma unroll
    for (int off = 1; off < 256; off <<= 1) {
        int u = (t >= off) ? sh[t - off] : 0;
        __syncthreads();
        sh[t] += u;
        __syncthreads();
    }
    g_boff[t] = sh[t] - v;
}

__global__ void scan_c_kernel(int N, int ET) {
    __shared__ int sh[256];
    int t = threadIdx.x;
    int idx = blockIdx.x * 256 + t;
    int c = (idx < N) ? g_cnt[idx] : 0;
    sh[t] = c;
    __syncthreads();
    #pragma unroll
    for (int off = 1; off < 256; off <<= 1) {
        int u = (t >= off) ? sh[t - off] : 0;
        __syncthreads();
        sh[t] += u;
        __syncthreads();
    }
    int ex = g_boff[blockIdx.x] + sh[t] - c;
    if (idx < N) {
        g_off[idx] = ex;
        g_cur[idx] = ex;
        if (idx == N - 1) g_off[N] = ET;
    }
}

// ---------------- 6: scatter (CSR fill) ----------------
__global__ void scatter_kernel(const unsigned* __restrict__ w, int E, int N) {
    __shared__ int s_st;
    if (threadIdx.x == 0) s_st = edge_stride(w);
    __syncthreads();
    int st = s_st;
    int i = blockIdx.x * blockDim.x + threadIdx.x;
    if (i >= E + N) return;
    int s, d;
    if (i < E) {
        s = (int)w[st * i];
        d = (int)w[st * E + st * i];
    } else {
        s = d = i - E;
    }
    int pos = atomicAdd(&g_cur[d], 1);
    g_src[pos] = s;
}

// ---------------- 7: fused softmax + aggregate + bias + mix-ELU ------------
__device__ __forceinline__ float mixelu(float z) {
    float e = z > 0.0f ? z : expm1f(z);
    return 0.5f * z + 0.5f * e;
}

__global__ void __launch_bounds__(256)
agg_kernel(float* __restrict__ out, const float* __restrict__ bias, int N) {
    int gt = blockIdx.x * blockDim.x + threadIdx.x;
    int d = gt >> 5;
    int lane = gt & 31;
    if (d >= N) return;
    int beg = g_off[d], end = g_off[d + 1];
    int head = lane >> 3;                        // 8 features per lane
    bool hsel = (head & 1) != 0;
    bool hhi = head >= 2;

    float4 ad4 = g_adst[d];
    float ad = hhi ? (hsel ? ad4.w : ad4.z) : (hsel ? ad4.y : ad4.x);

    float acc[8] = {0.f, 0.f, 0.f, 0.f, 0.f, 0.f, 0.f, 0.f};
    float se = 0.f;

    #pragma unroll 2
    for (int j = beg; j < end; j++) {
        int s = __ldg(&g_src[j]);
        float4 as4 = __ldg(&g_asrc[s]);
        float as = hhi ? (hsel ? as4.w : as4.z) : (hsel ? as4.y : as4.x);
        float e = __expf(lrelu(as + ad));
        se += e;
        uint4 u = __ldg((const uint4*)(g_hh + (size_t)s * 128) + lane);
        float2 p0 = __half22float2(*reinterpret_cast<__half2*>(&u.x));
        float2 p1 = __half22float2(*reinterpret_cast<__half2*>(&u.y));
        float2 p2 = __half22float2(*reinterpret_cast<__half2*>(&u.z));
        float2 p3 = __half22float2(*reinterpret_cast<__half2*>(&u.w));
        acc[0] = fmaf(e, p0.x, acc[0]); acc[1] = fmaf(e, p0.y, acc[1]);
        acc[2] = fmaf(e, p1.x, acc[2]); acc[3] = fmaf(e, p1.y, acc[3]);
        acc[4] = fmaf(e, p2.x, acc[4]); acc[5] = fmaf(e, p2.y, acc[5]);
        acc[6] = fmaf(e, p3.x, acc[6]); acc[7] = fmaf(e, p3.y, acc[7]);
    }

    float inv = 1.0f / (se + 1e-16f);
    const float* brow = bias + lane * 8;
    float o[8];
    #pragma unroll
    for (int c = 0; c < 8; c++)
        o[c] = mixelu(acc[c] * inv + __ldg(brow + c));

    float4* orow = (float4*)(out + (size_t)d * FTOT);
    orow[lane * 2]     = make_float4(o[0], o[1], o[2], o[3]);
    orow[lane * 2 + 1] = make_float4(o[4], o[5], o[6], o[7]);
}

// ---------------- launch ----------------
extern "C" void kernel_launch(void* const* d_in, const int* in_sizes, int n_in,
                              void* d_out, int out_size) {
    const float*    x       = (const float*)d_in[0];
    const unsigned* edge    = (const unsigned*)d_in[1];
    const float*    W       = (const float*)d_in[2];
    const float*    att_src = (const float*)d_in[3];
    const float*    att_dst = (const float*)d_in[4];
    const float*    bias    = (const float*)d_in[5];
    float*          out     = (float*)d_out;

    const int N = in_sizes[0] / IN_DIM;        // 50000
    const int E = in_sizes[1] / 2;             // 800000
    const int ET = E + N;
    const int GB = (N + 255) / 256;

    cudaFuncSetAttribute(gemm_kernel,
                         cudaFuncAttributeMaxDynamicSharedMemorySize, SMEM_BYTES);

    zero_cnt_kernel<<<(N + 255) / 256, 256>>>(N);                     // 1
    hist_kernel<<<(ET + 255) / 256, 256>>>(edge, E, N);               // 2
    wt_kernel<<<128, 256>>>(W);                                       // 3
    {
        dim3 grid((N + 127) / 128, HEADS);
        gemm_kernel<<<grid, 256, SMEM_BYTES>>>(x, att_src, att_dst, N); // 4 (profiled)
    }
    scan_a_kernel<<<GB, 256>>>(N);                                    // 5
    scan_b_kernel<<<1, 256>>>(GB);                                    // 6
    scan_c_kernel<<<GB, 256>>>(N, ET);                                // 7
    scatter_kernel<<<(ET + 255) / 256, 256>>>(edge, E, N);            // 8
    agg_kernel<<<((long)N * 32 + 255) / 256, 256>>>(out, bias, N);    // 9
}

// round 8
// speedup vs baseline: 1.2459x; 1.2459x over previous
#include <cuda_runtime.h>
#include <cuda_bf16.h>
#include <cuda_fp16.h>
#include <cstdint>

#define MAXN 50048
#define MAXE 860032
#define IN_DIM 128
#define HEADS 4
#define OUT_DIM 64
#define FTOT 256

// ---------------- scratch ----------------
__device__ unsigned g_hh[(size_t)MAXN * 128];   // h as half2 pairs: 25.6 MB
__device__ float4 g_asrc[MAXN];
__device__ float4 g_adst[MAXN];
__device__ int    g_src[MAXE];
__device__ int    g_cnt[MAXN];
__device__ int    g_off[MAXN + 1];
__device__ int    g_cur[MAXN];
__device__ int    g_bsum[256];
__device__ int    g_boff[256];
__device__ __align__(16) __half g_wt[FTOT * IN_DIM];  // W^T fp16: [n][k]

__device__ __forceinline__ float lrelu(float e) {
    return e > 0.0f ? e : 0.2f * e;
}

__device__ __forceinline__ int edge_stride(const unsigned* w) {
    int is64 = 1;
    #pragma unroll 1
    for (int j = 1; j < 64; j += 2)
        if (w[j] != 0u) { is64 = 0; break; }
    return is64 ? 2 : 1;
}

// ---------------- 1: zero degree counters ----------------
__global__ void zero_cnt_kernel(int N) {
    int i = blockIdx.x * blockDim.x + threadIdx.x;
    if (i < N) g_cnt[i] = 0;
}

// ---------------- 2: histogram ----------------
__global__ void hist_kernel(const unsigned* __restrict__ w, int E, int N) {
    __shared__ int s_st;
    if (threadIdx.x == 0) s_st = edge_stride(w);
    __syncthreads();
    int st = s_st;
    int i = blockIdx.x * blockDim.x + threadIdx.x;
    if (i >= E + N) return;
    int d = (i < E) ? (int)w[st * E + st * i] : (i - E);
    atomicAdd(&g_cnt[d], 1);
}

// ---------------- 3: W transpose -> fp16 ----------------
__global__ void wt_kernel(const float* __restrict__ W) {
    int i = blockIdx.x * 256 + threadIdx.x;     // 0..32767
    int k = i & 127, n = i >> 7;
    g_wt[i] = __float2half_rn(__ldg(W + (size_t)k * FTOT + n));
}

// ---------------- 4: GEMM on fp16 HMMA (single pass) ----------------
// Block: 256 thr (8 warps = 4m x 2n), tile 128 rows x 64 cols (one head).
// K staged in 2 chunks of 64 (R6-proven structure). A/B smem pitch 72 halves
// (conflict-free scalar fragment LDS). D = A@B^T in fp32 accum.
#define PA 72
#define SM_A 0
#define SM_B 18432
#define SM_ATT 33792                            // above the C region
#define SMEM_BYTES (SM_ATT + 512)

__global__ void __launch_bounds__(256)
gemm_kernel(const float* __restrict__ x,
            const float* __restrict__ att_src,
            const float* __restrict__ att_dst, int N) {
    extern __shared__ __align__(16) char sm[];
    __half* As = (__half*)(sm + SM_A);
    __half* Bs = (__half*)(sm + SM_B);
    float* attm = (float*)(sm + SM_ATT);

    const int tid = threadIdx.x;
    const int lane = tid & 31, wid = tid >> 5;
    const int mw = wid & 3, nw = wid >> 2;
    const int m_base = blockIdx.x * 128, head = blockIdx.y;
    const int n_base = head * OUT_DIM;

    if (tid < 64) {
        attm[tid] = __ldg(att_src + n_base + tid);
        attm[64 + tid] = __ldg(att_dst + n_base + tid);
    }

    float acc[2][4][4];
    #pragma unroll
    for (int mt = 0; mt < 2; mt++)
        #pragma unroll
        for (int nt = 0; nt < 4; nt++)
            #pragma unroll
            for (int c = 0; c < 4; c++) acc[mt][nt][c] = 0.0f;

    const int arow = tid >> 1, aseg = tid & 1;
    int grow = m_base + arow;
    if (grow >= N) grow = N - 1;

    const int aoff = (mw * 32 + (lane >> 2)) * PA + (lane & 3) * 2;
    const int boff = (nw * 32 + (lane >> 2)) * PA + (lane & 3) * 2;

    #pragma unroll 1
    for (int chunk = 0; chunk < 2; chunk++) {
        if (chunk) __syncthreads();
        // ---- A fill: 128 rows x 64 k -> fp16 ----
        {
            const float4* xs = (const float4*)(x + (size_t)grow * IN_DIM +
                                               chunk * 64 + aseg * 32);
            __half* ah = As + arow * PA + aseg * 32;
            #pragma unroll
            for (int i = 0; i < 8; i++) {
                float4 v = __ldg(xs + i);
                __half2 p0 = __floats2half2_rn(v.x, v.y);
                __half2 p1 = __floats2half2_rn(v.z, v.w);
                uint2 u;
                u.x = *reinterpret_cast<unsigned*>(&p0);
                u.y = *reinterpret_cast<unsigned*>(&p1);
                *(uint2*)(ah + i * 4) = u;
            }
        }
        // ---- B fill: 64 n-rows x 64 k from pre-transposed fp16 W^T ----
        {
            int bn = tid >> 2, q = tid & 3;
            const uint2* s = (const uint2*)(g_wt + (size_t)(n_base + bn) * IN_DIM + chunk * 64);
            uint2* d = (uint2*)(Bs + bn * PA);
            #pragma unroll
            for (int j = 0; j < 4; j++)
                d[q * 4 + j] = __ldg(s + q * 4 + j);
        }
        __syncthreads();

        // ---- single pass of HMMA over this K chunk ----
        #pragma unroll
        for (int kk = 0; kk < 64; kk += 16) {
            unsigned a[2][4], b[4][2];
            #pragma unroll
            for (int mt = 0; mt < 2; mt++) {
                const __half* p = As + aoff + mt * 16 * PA + kk;
                a[mt][0] = *(const unsigned*)(p);
                a[mt][1] = *(const unsigned*)(p + 8 * PA);
                a[mt][2] = *(const unsigned*)(p + 8);
                a[mt][3] = *(const unsigned*)(p + 8 * PA + 8);
            }
            #pragma unroll
            for (int nt = 0; nt < 4; nt++) {
                const __half* p = Bs + boff + nt * 8 * PA + kk;
                b[nt][0] = *(const unsigned*)(p);
                b[nt][1] = *(const unsigned*)(p + 8);
            }
            #pragma unroll
            for (int mt = 0; mt < 2; mt++)
                #pragma unroll
                for (int nt = 0; nt < 4; nt++)
                    asm volatile(
                        "mma.sync.aligned.m16n8k16.row.col.f32.f16.f16.f32 "
                        "{%0,%1,%2,%3}, {%4,%5,%6,%7}, {%8,%9}, {%0,%1,%2,%3};"
                        : "+f"(acc[mt][nt][0]), "+f"(acc[mt][nt][1]),
                          "+f"(acc[mt][nt][2]), "+f"(acc[mt][nt][3])
                        : "r"(a[mt][0]), "r"(a[mt][1]), "r"(a[mt][2]), "r"(a[mt][3]),
                          "r"(b[nt][0]), "r"(b[nt][1]));
        }
    }

    // ---- C -> smem (fp32, pitch 66) over A/B regions ----
    __syncthreads();
    float* Csm = (float*)(sm);                   // 128 x 66 floats = 33792 B
    #pragma unroll
    for (int mt = 0; mt < 2; mt++)
        #pragma unroll
        for (int nt = 0; nt < 4; nt++) {
            int r0 = mw * 32 + mt * 16 + (lane >> 2);
            int c = nw * 32 + nt * 8 + (lane & 3) * 2;
            *(float2*)(Csm + r0 * 66 + c) =
                make_float2(acc[mt][nt][0], acc[mt][nt][1]);
            *(float2*)(Csm + (r0 + 8) * 66 + c) =
                make_float2(acc[mt][nt][2], acc[mt][nt][3]);
        }
    __syncthreads();

    // ---- att logits (fp32) + fp16 h store ----
    {
        int r = tid >> 1, seg = tid & 1;
        int row = m_base + r;
        const float2* crow = (const float2*)(Csm + r * 66) + seg * 16;
        const float* asv = attm + seg * 32;
        const float* adv = attm + 64 + seg * 32;
        float s1 = 0.f, s2 = 0.f;
        uint4* dst = (uint4*)(g_hh + (size_t)row * 128) + head * 8 + seg * 4;
        #pragma unroll
        for (int q = 0; q < 4; q++) {
            uint4 pk;
            unsigned* pw = (unsigned*)&pk;
            #pragma unroll
            for (int j = 0; j < 4; j++) {
                float2 f = crow[q * 4 + j];
                s1 = fmaf(f.x, asv[q * 8 + j * 2], s1);
                s1 = fmaf(f.y, asv[q * 8 + j * 2 + 1], s1);
                s2 = fmaf(f.x, adv[q * 8 + j * 2], s2);
                s2 = fmaf(f.y, adv[q * 8 + j * 2 + 1], s2);
                __half2 hv = __floats2half2_rn(f.x, f.y);
                pw[j] = *reinterpret_cast<unsigned*>(&hv);
            }
            dst[q] = pk;
        }
        s1 += __shfl_xor_sync(0xffffffffu, s1, 1);
        s2 += __shfl_xor_sync(0xffffffffu, s2, 1);
        if (seg == 0 && row < N) {
            ((float*)&g_asrc[row])[head] = s1;
            ((float*)&g_adst[row])[head] = s2;
        }
    }
}

// ---------------- 5: three-phase exclusive scan ----------------
__global__ void scan_a_kernel(int N) {
    __shared__ int sh[256];
    int idx = blockIdx.x * 256 + threadIdx.x;
    int v = (idx < N) ? g_cnt[idx] : 0;
    sh[threadIdx.x] = v;
    __syncthreads();
    #pragma unroll
    for (int off = 128; off >= 1; off >>= 1) {
        if (threadIdx.x < off) sh[threadIdx.x] += sh[threadIdx.x + off];
        __syncthreads();
    }
    if (threadIdx.x == 0) g_bsum[blockIdx.x] = sh[0];
}

__global__ void scan_b_kernel(int GB) {
    __shared__ int sh[256];
    int t = threadIdx.x;
    int v = (t < GB) ? g_bsum[t] : 0;
    sh[t] = v;
    __syncthreads();
    #pragma unroll
    for (int off = 1; off < 256; off <<= 1) {
        int u = (t >= off) ? sh[t - off] : 0;
        __syncthreads();
        sh[t] += u;
        __syncthreads();
    }
    g_boff[t] = sh[t] - v;
}

__global__ void scan_c_kernel(int N, int ET) {
    __shared__ int sh[256];
    int t = threadIdx.x;
    int idx = blockIdx.x * 256 + t;
    int c = (idx < N) ? g_cnt[idx] : 0;
    sh[t] = c;
    __syncthreads();
    #pragma unroll
    for (int off = 1; off < 256; off <<= 1) {
        int u = (t >= off) ? sh[t - off] : 0;
        __syncthreads();
        sh[t] += u;
        __syncthreads();
    }
    int ex = g_boff[blockIdx.x] + sh[t] - c;
    if (idx < N) {
        g_off[idx] = ex;
        g_cur[idx] = ex;
        if (idx == N - 1) g_off[N] = ET;
    }
}

// ---------------- 6: scatter (CSR fill) ----------------
__global__ void scatter_kernel(const unsigned* __restrict__ w, int E, int N) {
    __shared__ int s_st;
    if (threadIdx.x == 0) s_st = edge_stride(w);
    __syncthreads();
    int st = s_st;
    int i = blockIdx.x * blockDim.x + threadIdx.x;
    if (i >= E + N) return;
    int s, d;
    if (i < E) {
        s = (int)w[st * i];
        d = (int)w[st * E + st * i];
    } else {
        s = d = i - E;
    }
    int pos = atomicAdd(&g_cur[d], 1);
    g_src[pos] = s;
}

// ---------------- 7: fused softmax + aggregate + bias + mix-ELU ------------
__device__ __forceinline__ float mixelu(float z) {
    float e = z > 0.0f ? z : expm1f(z);
    return 0.5f * z + 0.5f * e;
}

__global__ void __launch_bounds__(256)
agg_kernel(float* __restrict__ out, const float* __restrict__ bias, int N) {
    int gt = blockIdx.x * blockDim.x + threadIdx.x;
    int d = gt >> 5;
    int lane = gt & 31;
    if (d >= N) return;
    int beg = g_off[d], end = g_off[d + 1];
    int head = lane >> 3;                        // 8 features per lane
    bool hsel = (head & 1) != 0;
    bool hhi = head >= 2;

    float4 ad4 = g_adst[d];
    float ad = hhi ? (hsel ? ad4.w : ad4.z) : (hsel ? ad4.y : ad4.x);

    float acc[8] = {0.f, 0.f, 0.f, 0.f, 0.f, 0.f, 0.f, 0.f};
    float se = 0.f;

    #pragma unroll 2
    for (int j = beg; j < end; j++) {
        int s = __ldg(&g_src[j]);
        float4 as4 = __ldg(&g_asrc[s]);
        float as = hhi ? (hsel ? as4.w : as4.z) : (hsel ? as4.y : as4.x);
        float e = __expf(lrelu(as + ad));
        se += e;
        uint4 u = __ldg((const uint4*)(g_hh + (size_t)s * 128) + lane);
        float2 p0 = __half22float2(*reinterpret_cast<__half2*>(&u.x));
        float2 p1 = __half22float2(*reinterpret_cast<__half2*>(&u.y));
        float2 p2 = __half22float2(*reinterpret_cast<__half2*>(&u.z));
        float2 p3 = __half22float2(*reinterpret_cast<__half2*>(&u.w));
        acc[0] = fmaf(e, p0.x, acc[0]); acc[1] = fmaf(e, p0.y, acc[1]);
        acc[2] = fmaf(e, p1.x, acc[2]); acc[3] = fmaf(e, p1.y, acc[3]);
        acc[4] = fmaf(e, p2.x, acc[4]); acc[5] = fmaf(e, p2.y, acc[5]);
        acc[6] = fmaf(e, p3.x, acc[6]); acc[7] = fmaf(e, p3.y, acc[7]);
    }

    float inv = 1.0f / (se + 1e-16f);
    const float* brow = bias + lane * 8;
    float o[8];
    #pragma unroll
    for (int c = 0; c < 8; c++)
        o[c] = mixelu(acc[c] * inv + __ldg(brow + c));

    float4* orow = (float4*)(out + (size_t)d * FTOT);
    orow[lane * 2]     = make_float4(o[0], o[1], o[2], o[3]);
    orow[lane * 2 + 1] = make_float4(o[4], o[5], o[6], o[7]);
}

// ---------------- launch ----------------
extern "C" void kernel_launch(void* const* d_in, const int* in_sizes, int n_in,
                              void* d_out, int out_size) {
    const float*    x       = (const float*)d_in[0];
    const unsigned* edge    = (const unsigned*)d_in[1];
    const float*    W       = (const float*)d_in[2];
    const float*    att_src = (const float*)d_in[3];
    const float*    att_dst = (const float*)d_in[4];
    const float*    bias    = (const float*)d_in[5];
    float*          out     = (float*)d_out;

    const int N = in_sizes[0] / IN_DIM;        // 50000
    const int E = in_sizes[1] / 2;             // 800000
    const int ET = E + N;
    const int GB = (N + 255) / 256;

    cudaFuncSetAttribute(gemm_kernel,
                         cudaFuncAttributeMaxDynamicSharedMemorySize, SMEM_BYTES);

    zero_cnt_kernel<<<(N + 255) / 256, 256>>>(N);                     // 1
    hist_kernel<<<(ET + 255) / 256, 256>>>(edge, E, N);               // 2
    wt_kernel<<<128, 256>>>(W);                                       // 3
    {
        dim3 grid((N + 127) / 128, HEADS);
        gemm_kernel<<<grid, 256, SMEM_BYTES>>>(x, att_src, att_dst, N); // 4 (profiled)
    }
    scan_a_kernel<<<GB, 256>>>(N);                                    // 5
    scan_b_kernel<<<1, 256>>>(GB);                                    // 6
    scan_c_kernel<<<GB, 256>>>(N, ET);                                // 7
    scatter_kernel<<<(ET + 255) / 256, 256>>>(edge, E, N);            // 8
    agg_kernel<<<((long)N * 32 + 255) / 256, 256>>>(out, bias, N);    // 9
}

// round 9
// speedup vs baseline: 1.4670x; 1.1775x over previous
#include <cuda_runtime.h>
#include <cuda_bf16.h>
#include <cuda_fp16.h>
#include <cstdint>

#define MAXN 50048
#define MAXE 860032
#define IN_DIM 128
#define HEADS 4
#define OUT_DIM 64
#define FTOT 256

// ---------------- scratch ----------------
__device__ unsigned g_hh[(size_t)MAXN * 128];   // h as half2 pairs: 25.6 MB
__device__ float4 g_asrc[MAXN];
__device__ float4 g_adst[MAXN];
__device__ int    g_src[MAXE];
__device__ int    g_cnt[MAXN];
__device__ int    g_off[MAXN + 1];
__device__ int    g_cur[MAXN];
__device__ int    g_bsum[256];
__device__ int    g_boff[256];
__device__ __align__(16) __half g_wt[FTOT * IN_DIM];  // W^T fp16: [n][k]

__device__ __forceinline__ float lrelu(float e) {
    return e > 0.0f ? e : 0.2f * e;
}

__device__ __forceinline__ int edge_stride(const unsigned* w) {
    int is64 = 1;
    #pragma unroll 1
    for (int j = 1; j < 64; j += 2)
        if (w[j] != 0u) { is64 = 0; break; }
    return is64 ? 2 : 1;
}

// ---------------- 1: zero degree counters ----------------
__global__ void zero_cnt_kernel(int N) {
    int i = blockIdx.x * blockDim.x + threadIdx.x;
    if (i < N) g_cnt[i] = 0;
}

// ---------------- 2: histogram ----------------
__global__ void hist_kernel(const unsigned* __restrict__ w, int E, int N) {
    __shared__ int s_st;
    if (threadIdx.x == 0) s_st = edge_stride(w);
    __syncthreads();
    int st = s_st;
    int i = blockIdx.x * blockDim.x + threadIdx.x;
    if (i >= E + N) return;
    int d = (i < E) ? (int)w[st * E + st * i] : (i - E);
    atomicAdd(&g_cnt[d], 1);
}

// ---------------- 3: W transpose -> fp16 ----------------
__global__ void wt_kernel(const float* __restrict__ W) {
    int i = blockIdx.x * 256 + threadIdx.x;     // 0..32767
    int k = i & 127, n = i >> 7;
    g_wt[i] = __float2half_rn(__ldg(W + (size_t)k * FTOT + n));
}

// ---------------- 4: GEMM on fp16 HMMA ----------------
// Block: 256 thr (8 warps = 4m x 2n), tile 128 rows x 64 cols (one head).
// K staged in 2 chunks of 64; coalesced fills (8 lanes/row); epilogue stages
// half2 per-warp and writes g_hh coalesced (no fp32 Csm round-trip).
#define PA 72
#define SM_A 0
#define SM_B 18432
#define SMEM_BYTES 28160    // 27648 used

__global__ void __launch_bounds__(256)
gemm_kernel(const float* __restrict__ x, int N) {
    extern __shared__ __align__(16) char sm[];
    __half* As = (__half*)(sm + SM_A);
    __half* Bs = (__half*)(sm + SM_B);

    const int tid = threadIdx.x;
    const int lane = tid & 31, wid = tid >> 5;
    const int mw = wid & 3, nw = wid >> 2;
    const int m_base = blockIdx.x * 128, head = blockIdx.y;
    const int n_base = head * OUT_DIM;

    float acc[2][4][4];
    #pragma unroll
    for (int mt = 0; mt < 2; mt++)
        #pragma unroll
        for (int nt = 0; nt < 4; nt++)
            #pragma unroll
            for (int c = 0; c < 4; c++) acc[mt][nt][c] = 0.0f;

    const int ar = tid >> 3;                    // 0..31
    const int ac = tid & 7;                     // float4 / uint4 col idx
    const int aoff = (mw * 32 + (lane >> 2)) * PA + (lane & 3) * 2;
    const int boff = (nw * 32 + (lane >> 2)) * PA + (lane & 3) * 2;

    #pragma unroll 1
    for (int chunk = 0; chunk < 2; chunk++) {
        if (chunk) __syncthreads();
        // ---- A fill: 128 rows x 64 k -> fp16, coalesced (8 lanes/row) ----
        #pragma unroll
        for (int rr = 0; rr < 4; rr++) {
            int r = ar + rr * 32;
            int grow = m_base + r;
            if (grow >= N) grow = N - 1;
            const float4* xs = (const float4*)(x + (size_t)grow * IN_DIM + chunk * 64);
            #pragma unroll
            for (int p = 0; p < 2; p++) {
                float4 v = __ldg(xs + ac + p * 8);
                __half2 h0 = __floats2half2_rn(v.x, v.y);
                __half2 h1 = __floats2half2_rn(v.z, v.w);
                uint2 u;
                u.x = *reinterpret_cast<unsigned*>(&h0);
                u.y = *reinterpret_cast<unsigned*>(&h1);
                *(uint2*)(As + r * PA + (ac + p * 8) * 4) = u;
            }
        }
        // ---- B fill: 64 n-rows x 64 k, coalesced (8 lanes/row) ----
        #pragma unroll
        for (int rr = 0; rr < 2; rr++) {
            int n = ar + rr * 32;
            uint4 v = __ldg((const uint4*)(g_wt + (size_t)(n_base + n) * IN_DIM +
                                           chunk * 64) + ac);
            *(uint4*)(Bs + n * PA + ac * 8) = v;
        }
        __syncthreads();

        // ---- HMMA over this K chunk ----
        #pragma unroll
        for (int kk = 0; kk < 64; kk += 16) {
            unsigned a[2][4], b[4][2];
            #pragma unroll
            for (int mt = 0; mt < 2; mt++) {
                const __half* p = As + aoff + mt * 16 * PA + kk;
                a[mt][0] = *(const unsigned*)(p);
                a[mt][1] = *(const unsigned*)(p + 8 * PA);
                a[mt][2] = *(const unsigned*)(p + 8);
                a[mt][3] = *(const unsigned*)(p + 8 * PA + 8);
            }
            #pragma unroll
            for (int nt = 0; nt < 4; nt++) {
                const __half* p = Bs + boff + nt * 8 * PA + kk;
                b[nt][0] = *(const unsigned*)(p);
                b[nt][1] = *(const unsigned*)(p + 8);
            }
            #pragma unroll
            for (int mt = 0; mt < 2; mt++)
                #pragma unroll
                for (int nt = 0; nt < 4; nt++)
                    asm volatile(
                        "mma.sync.aligned.m16n8k16.row.col.f32.f16.f16.f32 "
                        "{%0,%1,%2,%3}, {%4,%5,%6,%7}, {%8,%9}, {%0,%1,%2,%3};"
                        : "+f"(acc[mt][nt][0]), "+f"(acc[mt][nt][1]),
                          "+f"(acc[mt][nt][2]), "+f"(acc[mt][nt][3])
                        : "r"(a[mt][0]), "r"(a[mt][1]), "r"(a[mt][2]), "r"(a[mt][3]),
                          "r"(b[nt][0]), "r"(b[nt][1]));
        }
    }

    // ---- epilogue: per-warp half2 staging -> coalesced g_hh stores ----
    __syncthreads();
    unsigned* stg = (unsigned*)sm + wid * (32 * 20);   // 2560B/warp, pitch 20
    #pragma unroll
    for (int mt = 0; mt < 2; mt++)
        #pragma unroll
        for (int nt = 0; nt < 4; nt++) {
            int rl = mt * 16 + (lane >> 2);
            int cu = nt * 4 + (lane & 3);
            __half2 lo = __floats2half2_rn(acc[mt][nt][0], acc[mt][nt][1]);
            __half2 hi = __floats2half2_rn(acc[mt][nt][2], acc[mt][nt][3]);
            stg[rl * 20 + cu] = *reinterpret_cast<unsigned*>(&lo);
            stg[(rl + 8) * 20 + cu] = *reinterpret_cast<unsigned*>(&hi);
        }
    __syncwarp();
    #pragma unroll
    for (int it = 0; it < 4; it++) {
        int rl = it * 8 + (lane >> 2);
        uint4 v = *(uint4*)(stg + rl * 20 + (lane & 3) * 4);
        int grow = m_base + mw * 32 + rl;
        *(uint4*)(g_hh + (size_t)grow * 128 + head * 32 + nw * 16 + (lane & 3) * 4) = v;
    }
}

// ---------------- 5: att logits from fp16 h (warp per node) ----------------
__global__ void __launch_bounds__(256)
att_kernel(const float* __restrict__ att_src,
           const float* __restrict__ att_dst, int N) {
    int gt = blockIdx.x * blockDim.x + threadIdx.x;
    int node = gt >> 5, lane = gt & 31;
    if (node >= N) return;
    uint4 u = __ldg((const uint4*)(g_hh + (size_t)node * 128) + lane);
    int head = lane >> 3;
    const float4* as4 = (const float4*)(att_src + head * OUT_DIM + (lane & 7) * 8);
    const float4* ad4 = (const float4*)(att_dst + head * OUT_DIM + (lane & 7) * 8);
    float4 a0 = __ldg(as4), a1 = __ldg(as4 + 1);
    float4 d0 = __ldg(ad4), d1 = __ldg(ad4 + 1);
    float2 p0 = __half22float2(*reinterpret_cast<__half2*>(&u.x));
    float2 p1 = __half22float2(*reinterpret_cast<__half2*>(&u.y));
    float2 p2 = __half22float2(*reinterpret_cast<__half2*>(&u.z));
    float2 p3 = __half22float2(*reinterpret_cast<__half2*>(&u.w));
    float s1 = p0.x * a0.x + p0.y * a0.y + p1.x * a0.z + p1.y * a0.w +
               p2.x * a1.x + p2.y * a1.y + p3.x * a1.z + p3.y * a1.w;
    float s2 = p0.x * d0.x + p0.y * d0.y + p1.x * d0.z + p1.y * d0.w +
               p2.x * d1.x + p2.y * d1.y + p3.x * d1.z + p3.y * d1.w;
    #pragma unroll
    for (int off = 4; off >= 1; off >>= 1) {
        s1 += __shfl_xor_sync(0xffffffffu, s1, off);
        s2 += __shfl_xor_sync(0xffffffffu, s2, off);
    }
    if ((lane & 7) == 0) {
        ((float*)&g_asrc[node])[head] = s1;
        ((float*)&g_adst[node])[head] = s2;
    }
}

// ---------------- 6: three-phase exclusive scan ----------------
__global__ void scan_a_kernel(int N) {
    __shared__ int sh[256];
    int idx = blockIdx.x * 256 + threadIdx.x;
    int v = (idx < N) ? g_cnt[idx] : 0;
    sh[threadIdx.x] = v;
    __syncthreads();
    #pragma unroll
    for (int off = 128; off >= 1; off >>= 1) {
        if (threadIdx.x < off) sh[threadIdx.x] += sh[threadIdx.x + off];
        __syncthreads();
    }
    if (threadIdx.x == 0) g_bsum[blockIdx.x] = sh[0];
}

__global__ void scan_b_kernel(int GB) {
    __shared__ int sh[256];
    int t = threadIdx.x;
    int v = (t < GB) ? g_bsum[t] : 0;
    sh[t] = v;
    __syncthreads();
    #pragma unroll
    for (int off = 1; off < 256; off <<= 1) {
        int u = (t >= off) ? sh[t - off] : 0;
        __syncthreads();
        sh[t] += u;
        __syncthreads();
    }
    g_boff[t] = sh[t] - v;
}

__global__ void scan_c_kernel(int N, int ET) {
    __shared__ int sh[256];
    int t = threadIdx.x;
    int idx = blockIdx.x * 256 + t;
    int c = (idx < N) ? g_cnt[idx] : 0;
    sh[t] = c;
    __syncthreads();
    #pragma unroll
    for (int off = 1; off < 256; off <<= 1) {
        int u = (t >= off) ? sh[t - off] : 0;
        __syncthreads();
        sh[t] += u;
        __syncthreads();
    }
    int ex = g_boff[blockIdx.x] + sh[t] - c;
    if (idx < N) {
        g_off[idx] = ex;
        g_cur[idx] = ex;
        if (idx == N - 1) g_off[N] = ET;
    }
}

// ---------------- 7: scatter (CSR fill) ----------------
__global__ void scatter_kernel(const unsigned* __restrict__ w, int E, int N) {
    __shared__ int s_st;
    if (threadIdx.x == 0) s_st = edge_stride(w);
    __syncthreads();
    int st = s_st;
    int i = blockIdx.x * blockDim.x + threadIdx.x;
    if (i >= E + N) return;
    int s, d;
    if (i < E) {
        s = (int)w[st * i];
        d = (int)w[st * E + st * i];
    } else {
        s = d = i - E;
    }
    int pos = atomicAdd(&g_cur[d], 1);
    g_src[pos] = s;
}

// ---------------- 8: fused softmax + aggregate + bias + mix-ELU ------------
__device__ __forceinline__ float mixelu(float z) {
    float e = z > 0.0f ? z : expm1f(z);
    return 0.5f * z + 0.5f * e;
}

__global__ void __launch_bounds__(256)
agg_kernel(float* __restrict__ out, const float* __restrict__ bias, int N) {
    int gt = blockIdx.x * blockDim.x + threadIdx.x;
    int d = gt >> 5;
    int lane = gt & 31;
    if (d >= N) return;
    int beg = g_off[d], end = g_off[d + 1];
    int head = lane >> 3;                        // 8 features per lane
    bool hsel = (head & 1) != 0;
    bool hhi = head >= 2;

    float4 ad4 = g_adst[d];
    float ad = hhi ? (hsel ? ad4.w : ad4.z) : (hsel ? ad4.y : ad4.x);

    float acc[8] = {0.f, 0.f, 0.f, 0.f, 0.f, 0.f, 0.f, 0.f};
    float se = 0.f;

    #pragma unroll 2
    for (int j = beg; j < end; j++) {
        int s = __ldg(&g_src[j]);
        float4 as4 = __ldg(&g_asrc[s]);
        float as = hhi ? (hsel ? as4.w : as4.z) : (hsel ? as4.y : as4.x);
        float e = __expf(lrelu(as + ad));
        se += e;
        uint4 u = __ldg((const uint4*)(g_hh + (size_t)s * 128) + lane);
        float2 p0 = __half22float2(*reinterpret_cast<__half2*>(&u.x));
        float2 p1 = __half22float2(*reinterpret_cast<__half2*>(&u.y));
        float2 p2 = __half22float2(*reinterpret_cast<__half2*>(&u.z));
        float2 p3 = __half22float2(*reinterpret_cast<__half2*>(&u.w));
        acc[0] = fmaf(e, p0.x, acc[0]); acc[1] = fmaf(e, p0.y, acc[1]);
        acc[2] = fmaf(e, p1.x, acc[2]); acc[3] = fmaf(e, p1.y, acc[3]);
        acc[4] = fmaf(e, p2.x, acc[4]); acc[5] = fmaf(e, p2.y, acc[5]);
        acc[6] = fmaf(e, p3.x, acc[6]); acc[7] = fmaf(e, p3.y, acc[7]);
    }

    float inv = 1.0f / (se + 1e-16f);
    const float* brow = bias + lane * 8;
    float o[8];
    #pragma unroll
    for (int c = 0; c < 8; c++)
        o[c] = mixelu(acc[c] * inv + __ldg(brow + c));

    float4* orow = (float4*)(out + (size_t)d * FTOT);
    orow[lane * 2]     = make_float4(o[0], o[1], o[2], o[3]);
    orow[lane * 2 + 1] = make_float4(o[4], o[5], o[6], o[7]);
}

// ---------------- launch ----------------
extern "C" void kernel_launch(void* const* d_in, const int* in_sizes, int n_in,
                              void* d_out, int out_size) {
    const float*    x       = (const float*)d_in[0];
    const unsigned* edge    = (const unsigned*)d_in[1];
    const float*    W       = (const float*)d_in[2];
    const float*    att_src = (const float*)d_in[3];
    const float*    att_dst = (const float*)d_in[4];
    const float*    bias    = (const float*)d_in[5];
    float*          out     = (float*)d_out;

    const int N = in_sizes[0] / IN_DIM;        // 50000
    const int E = in_sizes[1] / 2;             // 800000
    const int ET = E + N;
    const int GB = (N + 255) / 256;

    cudaFuncSetAttribute(gemm_kernel,
                         cudaFuncAttributeMaxDynamicSharedMemorySize, SMEM_BYTES);

    zero_cnt_kernel<<<(N + 255) / 256, 256>>>(N);                     // 1
    hist_kernel<<<(ET + 255) / 256, 256>>>(edge, E, N);               // 2
    wt_kernel<<<128, 256>>>(W);                                       // 3
    {
        dim3 grid((N + 127) / 128, HEADS);
        gemm_kernel<<<grid, 256, SMEM_BYTES>>>(x, N);                 // 4 (profiled)
    }
    att_kernel<<<((long)N * 32 + 255) / 256, 256>>>(att_src, att_dst, N); // 5
    scan_a_kernel<<<GB, 256>>>(N);                                    // 6
    scan_b_kernel<<<1, 256>>>(GB);                                    // 7
    scan_c_kernel<<<GB, 256>>>(N, ET);                                // 8
    scatter_kernel<<<(ET + 255) / 256, 256>>>(edge, E, N);            // 9
    agg_kernel<<<((long)N * 32 + 255) / 256, 256>>>(out, bias, N);    // 10
}